// round 10
// baseline (speedup 1.0000x reference)
#include <cuda_runtime.h>
#include <cuda_fp16.h>

// Problem constants
#define PW 32
#define PL 64
#define PK 512
#define PN 64
#define ROWS_PER_W (PL * PK)            // 32768
#define TOTAL_ROWS (PW * ROWS_PER_W)    // 1048576
#define EN_ELEMS   TOTAL_ROWS

// Scratch (no allocs allowed -> __device__ global)
__device__ unsigned long long  g_packed[TOTAL_ROWS];   // 8 MB: states rows as 64-bit masks

#define QT_STRIDE 72  // halves; padded -> conflict-free column reads

__device__ __forceinline__ void mma_f16(float* d, const unsigned* a, unsigned b0, unsigned b1) {
    asm volatile(
        "mma.sync.aligned.m16n8k16.row.col.f32.f16.f16.f32 "
        "{%0,%1,%2,%3}, {%4,%5,%6,%7}, {%8,%9}, {%0,%1,%2,%3};"
        : "+f"(d[0]), "+f"(d[1]), "+f"(d[2]), "+f"(d[3])
        : "r"(a[0]), "r"(a[1]), "r"(a[2]), "r"(a[3]), "r"(b0), "r"(b1));
}

// 2 bits -> fp16x2 {bit0 ? 1.0h : 0h, bit1 ? 1.0h : 0h}  (fp16 1.0 = 0x3C00)
__device__ __forceinline__ unsigned expand2(unsigned x) {
    return ((x & 1u) * 0x3C00u) | ((x & 2u) * 0x1E000000u);
}

// ---------------------------------------------------------------------------
// Kernel 0: pack states (fp32 0/1) into 64-bit row masks. Pure streaming:
// thread i handles byte (i&7) of row (i>>3): 8 consecutive floats -> 8 bits.
// Reads 268 MB coalesced, writes 8 MB. Trivially DRAM-bound.
// ---------------------------------------------------------------------------
__global__ void __launch_bounds__(256)
pack_kernel(const float* __restrict__ states) {
    const int i = blockIdx.x * 256 + threadIdx.x;   // < TOTAL_ROWS * 8
    const float4* p = reinterpret_cast<const float4*>(states) + (size_t)i * 2;
    const float4 a = p[0];
    const float4 b = p[1];
    unsigned bits = 0;
    bits |= (a.x != 0.0f) ? 0x01u : 0u;
    bits |= (a.y != 0.0f) ? 0x02u : 0u;
    bits |= (a.z != 0.0f) ? 0x04u : 0u;
    bits |= (a.w != 0.0f) ? 0x08u : 0u;
    bits |= (b.x != 0.0f) ? 0x10u : 0u;
    bits |= (b.y != 0.0f) ? 0x20u : 0u;
    bits |= (b.z != 0.0f) ? 0x40u : 0u;
    bits |= (b.w != 0.0f) ? 0x80u : 0u;
    reinterpret_cast<unsigned char*>(g_packed)[i] = (unsigned char)bits;
}

// ---------------------------------------------------------------------------
// Kernel 1: energies via fp16-split MMA from PACKED bits.
//   Q = hi + lo (2x fp16, ~23 mantissa bits); s in {0,1} exact in fp16 ->
//   fp32-equivalent energies. A fragments expanded from bit masks in
//   registers (reads 8 MB instead of 268 MB -> no streaming-load stalls).
//   R6-proven shape: warp owns 64 rows (4 blocks of 16), nt-outer loop with
//   fold-early scalar accumulation, B fragments shared across blocks.
// ---------------------------------------------------------------------------
__global__ void __launch_bounds__(256, 2)
energies_kernel(const float* __restrict__ Qg,
                float* __restrict__ energies_out) {
    const int w   = blockIdx.y;    // 0..31
    const int cta = blockIdx.x;    // 0..63
    const int tid = threadIdx.x;

    __shared__ __half sQT[2][PN * QT_STRIDE];

    // Build Q^T fp16 splits in smem (Q = hi + lo)
    const float* Qw = Qg + (size_t)w * PN * PN;
    for (int idx = tid; idx < PN * PN; idx += 256) {
        const int i = idx >> 6;
        const int j = idx & 63;
        float q = Qw[idx];
        __half h = __float2half_rn(q);
        float r = q - __half2float(h);
        __half lo = __float2half_rn(r);
        sQT[0][j * QT_STRIDE + i] = h;
        sQT[1][j * QT_STRIDE + i] = lo;
    }
    __syncthreads();

    const int warp = tid >> 5;
    const int lane = tid & 31;
    const int g  = lane >> 2;  // 0..7
    const int tg = lane & 3;   // 0..3

    const int row_base = w * ROWS_PER_W + cta * 512 + warp * 64;

    // A fragments for 4 blocks of 16 rows, expanded from packed bits.
    // Lanes of a tg-quad read the same uint2 -> L1 broadcast.
    unsigned af[4][4][4];
    const uint2* packed = reinterpret_cast<const uint2*>(g_packed);
    #pragma unroll
    for (int bi = 0; bi < 4; bi++) {
        const uint2 bg = packed[row_base + bi * 16 + g];
        const uint2 b8 = packed[row_base + bi * 16 + 8 + g];
        #pragma unroll
        for (int kc = 0; kc < 4; kc++) {
            const unsigned wl = (kc < 2) ? bg.x : bg.y;
            const unsigned wh = (kc < 2) ? b8.x : b8.y;
            const int sb = (kc & 1) * 16 + tg * 2;
            af[bi][kc][0] = expand2((wl >> sb) & 3u);
            af[bi][kc][1] = expand2((wh >> sb) & 3u);
            af[bi][kc][2] = expand2((wl >> (sb + 8)) & 3u);
            af[bi][kc][3] = expand2((wh >> (sb + 8)) & 3u);
        }
    }

    float eg[4]  = {0.f, 0.f, 0.f, 0.f};
    float eg8[4] = {0.f, 0.f, 0.f, 0.f};

    #pragma unroll
    for (int nt = 0; nt < 8; nt++) {
        const int kc0 = nt >> 1;
        const int rlo = (nt & 1) ? 2 : 0;
        const int rhi = (nt & 1) ? 3 : 1;

        float d[4][4];
        #pragma unroll
        for (int bi = 0; bi < 4; bi++)
            #pragma unroll
            for (int e = 0; e < 4; e++) d[bi][e] = 0.0f;

        const int n = nt * 8 + g;
        #pragma unroll
        for (int sp = 0; sp < 2; sp++) {
            const __half* qt = sQT[sp] + n * QT_STRIDE + tg * 2;
            unsigned b0[4], b1[4];
            #pragma unroll
            for (int kc = 0; kc < 4; kc++) {
                b0[kc] = *reinterpret_cast<const unsigned*>(qt + kc * 16);
                b1[kc] = *reinterpret_cast<const unsigned*>(qt + kc * 16 + 8);
            }
            #pragma unroll
            for (int kc = 0; kc < 4; kc++)
                #pragma unroll
                for (int bi = 0; bi < 4; bi++)
                    mma_f16(d[bi], af[bi][kc], b0[kc], b1[kc]);
        }

        // Fold this nt's 8 j-columns into scalar energies (s bits live in af).
        #pragma unroll
        for (int bi = 0; bi < 4; bi++) {
            unsigned a = af[bi][kc0][rlo];
            if (a & 0xFFFFu) eg[bi]  += d[bi][0];
            if (a >> 16)     eg[bi]  += d[bi][1];
            a = af[bi][kc0][rhi];
            if (a & 0xFFFFu) eg8[bi] += d[bi][2];
            if (a >> 16)     eg8[bi] += d[bi][3];
        }
    }

    // Epilogue: reduce over tg, store energies (bits already in g_packed).
    #pragma unroll
    for (int bi = 0; bi < 4; bi++) {
        float e0 = eg[bi], e8 = eg8[bi];
        e0 += __shfl_xor_sync(0xffffffffu, e0, 1);
        e0 += __shfl_xor_sync(0xffffffffu, e0, 2);
        e8 += __shfl_xor_sync(0xffffffffu, e8, 1);
        e8 += __shfl_xor_sync(0xffffffffu, e8, 2);
        if (tg == 0) {
            const int r0 = row_base + bi * 16 + g;
            energies_out[r0]     = e0;
            energies_out[r0 + 8] = e8;
        }
    }
}

// ---------------------------------------------------------------------------
// Kernel 2: fused mask + row-gather swap, LANE-COALESCED stores (R9-proven).
//   Warp owns 8 consecutive rows; lane computes the swap decision for row
//   (lane&7), then each STG.128 covers 512 contiguous bytes.
// ---------------------------------------------------------------------------
__global__ void __launch_bounds__(256)
swap_kernel(const float* __restrict__ energies,
            const float* __restrict__ beta,
            const float* __restrict__ u,
            float* __restrict__ out_states) {
    const int gwarp = (blockIdx.x * 256 + threadIdx.x) >> 5;  // 0 .. TOTAL_ROWS/8-1
    const int lane  = threadIdx.x & 31;
    const int row0  = gwarp << 3;

    const int r = row0 + (lane & 7);
    const int k = r & 511;
    const int l = (r >> 9) & 63;
    const int w = r >> 15;
    const int j = (l == 0) ? 0 : (l - 1);
    const float e1 = energies[(w * PL + j) * PK + k];
    const float e2 = energies[(w * PL + j + 1) * PK + k];
    const float db = beta[j + 1] - beta[j];
    const bool  m  = u[(w * 63 + j) * PK + k] < expf((e2 - e1) * db);
    int src;
    if (l == 0) src = m ? 1 : 0;
    else        src = m ? (l - 1) : l;
    const int my_src_row = (w * PL + src) * PK + k;

    const uint2* packed = reinterpret_cast<const uint2*>(g_packed);
    float4* out4 = reinterpret_cast<float4*>(out_states) + ((size_t)row0 << 4);

    #pragma unroll
    for (int qq = 0; qq < 4; qq++) {
        const int c   = qq * 32 + lane;   // float4 chunk 0..127 within warp block
        const int rib = c >> 4;           // row-in-block 0..7
        const int sub = c & 15;           // float4 index within row
        const int src_row = __shfl_sync(0xffffffffu, my_src_row, rib);
        const uint2 pk = packed[src_row];
        const unsigned word = (sub & 8) ? pk.y : pk.x;
        const unsigned nib  = (word >> ((sub & 7) * 4)) & 0xFu;
        float4 v;
        v.x = (nib & 1u) ? 1.0f : 0.0f;
        v.y = (nib & 2u) ? 1.0f : 0.0f;
        v.z = (nib & 4u) ? 1.0f : 0.0f;
        v.w = (nib & 8u) ? 1.0f : 0.0f;
        __stcs(out4 + c, v);   // streaming store: output never re-read
    }
}

// ---------------------------------------------------------------------------

extern "C" void kernel_launch(void* const* d_in, const int* in_sizes, int n_in,
                              void* d_out, int out_size) {
    const float* states = (const float*)d_in[0];  // (32,64,512,64) f32
    const float* Q      = (const float*)d_in[1];  // (32,64,64) f32
    const float* beta   = (const float*)d_in[2];  // (64,) f32
    const float* u      = (const float*)d_in[3];  // (32,63,512) f32

    float* energies   = (float*)d_out;
    float* out_states = (float*)d_out + EN_ELEMS;

    pack_kernel<<<(TOTAL_ROWS * 8) / 256, 256>>>(states);

    dim3 egrid(64, PW);
    energies_kernel<<<egrid, 256>>>(Q, energies);

    swap_kernel<<<(TOTAL_ROWS * 4) / 256, 256>>>(energies, beta, u, out_states);
}